// round 1
// baseline (speedup 1.0000x reference)
#include <cuda_runtime.h>

#define D_MODEL 1024
#define HALF    32
#define T_LEN   8192
#define BATCH   4
#define ROWS    (BATCH * T_LEN)   // 32768
#define TAPS    64
#define TT      64                // time tile (conv+gemm2 block)
#define RB      64                // rows per block (gemm1)

// scratch: projected modes xp[row][n]  (4 MB)
__device__ float g_xp[ROWS * HALF];

// ---------------------------------------------------------------------------
// GEMM1: xp[row][n] = sum_d x[row][d] * W_in[n][d]
// block: 256 threads, 64 rows, all 32 n.
// thread: n = tid&31, owns 8 rows (warp rg = tid>>5 handles rows rg*8..rg*8+7).
// x chunk staged in smem (broadcast LDS.128), W chunk in registers.
// ---------------------------------------------------------------------------
__global__ __launch_bounds__(256) void proj_kernel(const float* __restrict__ x,
                                                   const float* __restrict__ W_in)
{
    __shared__ float xs[RB][32];
    const int tid  = threadIdx.x;
    const int n    = tid & 31;
    const int rg   = tid >> 5;           // 0..7
    const int row0 = blockIdx.x * RB;

    float acc[8];
#pragma unroll
    for (int r = 0; r < 8; r++) acc[r] = 0.f;

    // loader mapping: thread loads 8 contiguous floats of one row
    const int lr = tid >> 2;             // 0..63
    const int lc = (tid & 3) * 8;        // 0,8,16,24

    for (int dc = 0; dc < D_MODEL / 32; dc++) {
        const int d0 = dc * 32;
        const float4* src = (const float4*)(x + (size_t)(row0 + lr) * D_MODEL + d0 + lc);
        float4 a0 = src[0];
        float4 a1 = src[1];
        *(float4*)&xs[lr][lc]     = a0;
        *(float4*)&xs[lr][lc + 4] = a1;
        __syncthreads();

        // this thread's W chunk (row n, 32 d) in registers
        float4 w[8];
        const float4* wp = (const float4*)(W_in + (size_t)n * D_MODEL + d0);
#pragma unroll
        for (int k = 0; k < 8; k++) w[k] = wp[k];

#pragma unroll
        for (int r = 0; r < 8; r++) {
            const float4* xr = (const float4*)&xs[rg * 8 + r][0];
#pragma unroll
            for (int k = 0; k < 8; k++) {
                float4 xv = xr[k];
                acc[r] += xv.x * w[k].x;
                acc[r] += xv.y * w[k].y;
                acc[r] += xv.z * w[k].z;
                acc[r] += xv.w * w[k].w;
            }
        }
        __syncthreads();
    }

#pragma unroll
    for (int r = 0; r < 8; r++) {
        g_xp[(size_t)(row0 + rg * 8 + r) * HALF + n] = acc[r];
    }
}

// ---------------------------------------------------------------------------
// Kernel 2: fused  (a) build 64-tap FIR kernel K[n][s]
//                  (b) causal conv  y[t][n] = sum_s K[n][s]*xp[t-s][n]
//                  (c) GEMM2 out[t][d] = sum_n y[t][n]*W_out[d][n]
// block: one (b, 64-t tile); 256 threads.
// ---------------------------------------------------------------------------
__global__ __launch_bounds__(256) void conv_out_kernel(
    const float* __restrict__ log_tau, const float* __restrict__ freq,
    const float* __restrict__ Bp,      const float* __restrict__ Cp,
    const float* __restrict__ log_dt,  const float* __restrict__ W_out,
    float* __restrict__ out)
{
    __shared__ float xp_s[127 * 32];       // j=0..126 <-> tq = t0-63+j
    __shared__ float kk[TAPS][32];         // kk[s][n]
    __shared__ float y_s[TT][32];
    __shared__ float pg[32], pl[32], pa[32];

    const int tid = threadIdx.x;
    const int blk = blockIdx.x;
    const int b   = blk >> 7;              // / 128 tiles per batch
    const int t0  = (blk & 127) * TT;

    if (tid < 32) {
        float dt  = expf(log_dt[0]);
        float tau = fmaxf(expf(log_tau[tid]), 1e-4f);
        pl[tid] = -tau * dt;
        pa[tid] = freq[tid] * dt;
        pg[tid] = logf(fabsf(Bp[tid]) + 1e-9f) + logf(fabsf(Cp[tid]) + 1e-9f);
    }

    // stage xp history tile (zero-padded before batch start)
    for (int idx = tid; idx < 127 * 32; idx += 256) {
        const int j = idx >> 5, n = idx & 31;
        const int tq = t0 - 63 + j;
        xp_s[idx] = (tq >= 0) ? g_xp[((size_t)b * T_LEN + tq) * HALF + n] : 0.f;
    }
    __syncthreads();

    // FIR taps
    for (int idx = tid; idx < TAPS * 32; idx += 256) {
        const int s = idx >> 5, n = idx & 31;
        kk[s][n] = expf(pg[n] + (float)s * pl[n]) * cosf((float)s * pa[n]);
    }
    __syncthreads();

    // causal conv: thread handles n = tid&31, 8 time steps
    {
        const int n  = tid & 31;
        const int tg = tid >> 5;
#pragma unroll
        for (int r = 0; r < 8; r++) {
            const int tl = tg * 8 + r;
            float acc = 0.f;
            const float* base = &xp_s[(tl + 63) * 32 + n];
#pragma unroll
            for (int s = 0; s < TAPS; s++) {
                acc += kk[s][n] * base[-s * 32];
            }
            y_s[tl][n] = acc;
        }
    }
    __syncthreads();

    // GEMM2: thread owns 4 consecutive d columns (d0 = tid*4), tiles 8 t at a time
    const int d0 = tid * 4;
#pragma unroll 1
    for (int ttile = 0; ttile < TT / 8; ttile++) {
        const int tb = ttile * 8;
        float acc[8][4];
#pragma unroll
        for (int i = 0; i < 8; i++)
#pragma unroll
            for (int j = 0; j < 4; j++) acc[i][j] = 0.f;

#pragma unroll
        for (int nc = 0; nc < 4; nc++) {
            const int n0 = nc * 8;
            float4 w[4][2];
#pragma unroll
            for (int dd = 0; dd < 4; dd++) {
                const float4* wp = (const float4*)(W_out + (size_t)(d0 + dd) * HALF + n0);
                w[dd][0] = wp[0];
                w[dd][1] = wp[1];
            }
#pragma unroll
            for (int t8 = 0; t8 < 8; t8++) {
                float4 y0 = *(const float4*)&y_s[tb + t8][n0];
                float4 y1 = *(const float4*)&y_s[tb + t8][n0 + 4];
#pragma unroll
                for (int dd = 0; dd < 4; dd++) {
                    acc[t8][dd] += y0.x * w[dd][0].x;
                    acc[t8][dd] += y0.y * w[dd][0].y;
                    acc[t8][dd] += y0.z * w[dd][0].z;
                    acc[t8][dd] += y0.w * w[dd][0].w;
                    acc[t8][dd] += y1.x * w[dd][1].x;
                    acc[t8][dd] += y1.y * w[dd][1].y;
                    acc[t8][dd] += y1.z * w[dd][1].z;
                    acc[t8][dd] += y1.w * w[dd][1].w;
                }
            }
        }
#pragma unroll
        for (int t8 = 0; t8 < 8; t8++) {
            float4 o;
            o.x = acc[t8][0]; o.y = acc[t8][1]; o.z = acc[t8][2]; o.w = acc[t8][3];
            *(float4*)(out + ((size_t)b * T_LEN + t0 + tb + t8) * D_MODEL + d0) = o;
        }
    }
}

// ---------------------------------------------------------------------------
extern "C" void kernel_launch(void* const* d_in, const int* in_sizes, int n_in,
                              void* d_out, int out_size)
{
    const float* x       = (const float*)d_in[0];
    const float* log_tau = (const float*)d_in[1];
    const float* freq    = (const float*)d_in[2];
    const float* Bp      = (const float*)d_in[3];
    const float* Cp      = (const float*)d_in[4];
    const float* log_dt  = (const float*)d_in[5];
    const float* W_in    = (const float*)d_in[6];
    const float* W_out   = (const float*)d_in[7];
    float* out           = (float*)d_out;

    (void)in_sizes; (void)n_in; (void)out_size;

    proj_kernel<<<ROWS / RB, 256>>>(x, W_in);
    conv_out_kernel<<<(BATCH * T_LEN) / TT, 256>>>(log_tau, freq, Bp, Cp, log_dt,
                                                   W_out, out);
}

// round 3
// speedup vs baseline: 1.1717x; 1.1717x over previous
#include <cuda_runtime.h>
#include <cstdint>

#define D_MODEL 1024
#define HALF    32
#define T_LEN   8192
#define BATCH   4
#define ROWS    (BATCH * T_LEN)   // 32768
#define TAPS    64
#define TT      64

// scratch: projected modes xp[row][n]  (4 MB)
__device__ float g_xp[ROWS * HALF];

__device__ __forceinline__ float tf32_rna(float v) {
    uint32_t b;
    asm("cvt.rna.tf32.f32 %0, %1;" : "=r"(b) : "f"(v));
    return __uint_as_float(b);
}

__device__ __forceinline__ void mma_tf32(float& c0, float& c1, float& c2, float& c3,
                                         uint32_t a0, uint32_t a1, uint32_t a2, uint32_t a3,
                                         uint32_t b0, uint32_t b1) {
    asm volatile(
        "mma.sync.aligned.m16n8k8.row.col.f32.tf32.tf32.f32 "
        "{%0,%1,%2,%3}, {%4,%5,%6,%7}, {%8,%9}, {%0,%1,%2,%3};"
        : "+f"(c0), "+f"(c1), "+f"(c2), "+f"(c3)
        : "r"(a0), "r"(a1), "r"(a2), "r"(a3), "r"(b0), "r"(b1));
}

// ---------------------------------------------------------------------------
// SMEM layout for GEMM1 (floats, stride-36 rows for conflict-free access)
// A: 128 rows x 32 k  (hi, lo)   B: 32 n x 32 k (hi, lo)
// ---------------------------------------------------------------------------
#define ASTR 36
#define A_ELEMS (128 * ASTR)
#define B_ELEMS (32 * ASTR)

struct SmemG1 {
    float Ah[A_ELEMS];
    float Al[A_ELEMS];
    float Bh[B_ELEMS];
    float Bl[B_ELEMS];
};
#define SMEM_G1_BYTES sizeof(SmemG1)

// ===========================================================================
// GEMM1: xp[row][n] = sum_d x[row][d] * W_in[n][d]
// mma.sync tf32 with 3xTF32 split. CTA 256 thr = 8 warps.
// Warp w: rows (w&3)*32 .. +32, cols (w>>2)*16 .. +16.
// K = 1024 in 32 chunks of 32 (4 k-steps of 8 per chunk).
// ===========================================================================
__global__ void __launch_bounds__(256) proj_mma_kernel(const float* __restrict__ x,
                                                       const float* __restrict__ W_in)
{
    extern __shared__ SmemG1 sm[];
    const int tid = threadIdx.x;
    const int wid = tid >> 5;
    const int lid = tid & 31;
    const int g   = lid >> 2;      // groupID 0..7
    const int tig = lid & 3;       // thread-in-group
    const int row0 = blockIdx.x * 128;

    const int mroww = (wid & 3) * 32;
    const int ncolw = (wid >> 2) * 16;

    // ---- prefetch helpers: thread covers flat float4 indices ----
    // A: 128 rows x 32 k = 1024 float4 -> 4 per thread
    // B: 32 n x 32 k = 256 float4 -> 1 per thread
    float4 pa[4];
    float4 pb;

    {
        // prefetch chunk 0
#pragma unroll
        for (int p = 0; p < 4; p++) {
            const int f = tid + p * 256;
            const int r = f >> 3, q = f & 7;
            pa[p] = *(const float4*)(x + (size_t)(row0 + r) * D_MODEL + q * 4);
        }
        {
            const int n = tid >> 3, q = tid & 7;
            pb = *(const float4*)(W_in + (size_t)n * D_MODEL + q * 4);
        }
        // split + store
#pragma unroll
        for (int p = 0; p < 4; p++) {
            const int f = tid + p * 256;
            const int r = f >> 3, q = f & 7;
            float4 v = pa[p], h, l;
            h.x = tf32_rna(v.x); l.x = tf32_rna(v.x - h.x);
            h.y = tf32_rna(v.y); l.y = tf32_rna(v.y - h.y);
            h.z = tf32_rna(v.z); l.z = tf32_rna(v.z - h.z);
            h.w = tf32_rna(v.w); l.w = tf32_rna(v.w - h.w);
            *(float4*)&sm->Ah[r * ASTR + q * 4] = h;
            *(float4*)&sm->Al[r * ASTR + q * 4] = l;
        }
        {
            const int n = tid >> 3, q = tid & 7;
            float4 v = pb, h, l;
            h.x = tf32_rna(v.x); l.x = tf32_rna(v.x - h.x);
            h.y = tf32_rna(v.y); l.y = tf32_rna(v.y - h.y);
            h.z = tf32_rna(v.z); l.z = tf32_rna(v.z - h.z);
            h.w = tf32_rna(v.w); l.w = tf32_rna(v.w - h.w);
            *(float4*)&sm->Bh[n * ASTR + q * 4] = h;
            *(float4*)&sm->Bl[n * ASTR + q * 4] = l;
        }
    }

    float acc[2][2][4];
#pragma unroll
    for (int mt = 0; mt < 2; mt++)
#pragma unroll
        for (int nt = 0; nt < 2; nt++)
#pragma unroll
            for (int i = 0; i < 4; i++) acc[mt][nt][i] = 0.f;

    const uint32_t* Ahu = (const uint32_t*)sm->Ah;
    const uint32_t* Alu = (const uint32_t*)sm->Al;
    const uint32_t* Bhu = (const uint32_t*)sm->Bh;
    const uint32_t* Blu = (const uint32_t*)sm->Bl;

#pragma unroll 1
    for (int c = 0; c < 32; c++) {
        __syncthreads();   // smem for chunk c ready

        // prefetch chunk c+1 into registers
        if (c + 1 < 32) {
#pragma unroll
            for (int p = 0; p < 4; p++) {
                const int f = tid + p * 256;
                const int r = f >> 3, q = f & 7;
                pa[p] = *(const float4*)(x + (size_t)(row0 + r) * D_MODEL +
                                         (c + 1) * 32 + q * 4);
            }
            {
                const int n = tid >> 3, q = tid & 7;
                pb = *(const float4*)(W_in + (size_t)n * D_MODEL + (c + 1) * 32 + q * 4);
            }
        }

        // compute: 4 k-steps of 8
#pragma unroll
        for (int s = 0; s < 4; s++) {
            const int k0 = s * 8 + tig;
            uint32_t ah[2][4], al[2][4], bh[2][2], bl[2][2];
#pragma unroll
            for (int mt = 0; mt < 2; mt++) {
                const int r = mroww + mt * 16 + g;
                ah[mt][0] = Ahu[r * ASTR + k0];
                ah[mt][1] = Ahu[(r + 8) * ASTR + k0];
                ah[mt][2] = Ahu[r * ASTR + k0 + 4];
                ah[mt][3] = Ahu[(r + 8) * ASTR + k0 + 4];
                al[mt][0] = Alu[r * ASTR + k0];
                al[mt][1] = Alu[(r + 8) * ASTR + k0];
                al[mt][2] = Alu[r * ASTR + k0 + 4];
                al[mt][3] = Alu[(r + 8) * ASTR + k0 + 4];
            }
#pragma unroll
            for (int nt = 0; nt < 2; nt++) {
                const int n = ncolw + nt * 8 + g;
                bh[nt][0] = Bhu[n * ASTR + k0];
                bh[nt][1] = Bhu[n * ASTR + k0 + 4];
                bl[nt][0] = Blu[n * ASTR + k0];
                bl[nt][1] = Blu[n * ASTR + k0 + 4];
            }
#pragma unroll
            for (int mt = 0; mt < 2; mt++)
#pragma unroll
                for (int nt = 0; nt < 2; nt++) {
                    float* cc = acc[mt][nt];
                    mma_tf32(cc[0], cc[1], cc[2], cc[3],
                             ah[mt][0], ah[mt][1], ah[mt][2], ah[mt][3],
                             bh[nt][0], bh[nt][1]);
                    mma_tf32(cc[0], cc[1], cc[2], cc[3],
                             ah[mt][0], ah[mt][1], ah[mt][2], ah[mt][3],
                             bl[nt][0], bl[nt][1]);
                    mma_tf32(cc[0], cc[1], cc[2], cc[3],
                             al[mt][0], al[mt][1], al[mt][2], al[mt][3],
                             bh[nt][0], bh[nt][1]);
                }
        }

        __syncthreads();   // all reads of chunk c done

        // store prefetched chunk c+1 (split hi/lo)
        if (c + 1 < 32) {
#pragma unroll
            for (int p = 0; p < 4; p++) {
                const int f = tid + p * 256;
                const int r = f >> 3, q = f & 7;
                float4 v = pa[p], h, l;
                h.x = tf32_rna(v.x); l.x = tf32_rna(v.x - h.x);
                h.y = tf32_rna(v.y); l.y = tf32_rna(v.y - h.y);
                h.z = tf32_rna(v.z); l.z = tf32_rna(v.z - h.z);
                h.w = tf32_rna(v.w); l.w = tf32_rna(v.w - h.w);
                *(float4*)&sm->Ah[r * ASTR + q * 4] = h;
                *(float4*)&sm->Al[r * ASTR + q * 4] = l;
            }
            {
                const int n = tid >> 3, q = tid & 7;
                float4 v = pb, h, l;
                h.x = tf32_rna(v.x); l.x = tf32_rna(v.x - h.x);
                h.y = tf32_rna(v.y); l.y = tf32_rna(v.y - h.y);
                h.z = tf32_rna(v.z); l.z = tf32_rna(v.z - h.z);
                h.w = tf32_rna(v.w); l.w = tf32_rna(v.w - h.w);
                *(float4*)&sm->Bh[n * ASTR + q * 4] = h;
                *(float4*)&sm->Bl[n * ASTR + q * 4] = l;
            }
        }
    }

    // epilogue: c0,c1 -> (row g, col 2*tig), c2,c3 -> (row g+8)
#pragma unroll
    for (int mt = 0; mt < 2; mt++) {
        const int r0 = row0 + mroww + mt * 16 + g;
#pragma unroll
        for (int nt = 0; nt < 2; nt++) {
            const int col = ncolw + nt * 8 + tig * 2;
            float2 v0, v1;
            v0.x = acc[mt][nt][0]; v0.y = acc[mt][nt][1];
            v1.x = acc[mt][nt][2]; v1.y = acc[mt][nt][3];
            *(float2*)(g_xp + (size_t)r0 * HALF + col)       = v0;
            *(float2*)(g_xp + (size_t)(r0 + 8) * HALF + col) = v1;
        }
    }
}

// ===========================================================================
// Kernel 2: FIR taps + causal conv + GEMM2 (out = y * W_out^T)
// ===========================================================================
__global__ void __launch_bounds__(256, 2) conv_out_kernel(
    const float* __restrict__ log_tau, const float* __restrict__ freq,
    const float* __restrict__ Bp,      const float* __restrict__ Cp,
    const float* __restrict__ log_dt,  const float* __restrict__ W_out,
    float* __restrict__ out)
{
    __shared__ float xp_s[127 * 32];
    __shared__ float kk[TAPS][32];
    __shared__ float y_s[TT][32];
    __shared__ float pg[32], pl[32], pa[32];

    const int tid = threadIdx.x;
    const int blk = blockIdx.x;
    const int b   = blk >> 7;
    const int t0  = (blk & 127) * TT;

    if (tid < 32) {
        float dt  = expf(log_dt[0]);
        float tau = fmaxf(expf(log_tau[tid]), 1e-4f);
        pl[tid] = -tau * dt;
        pa[tid] = freq[tid] * dt;
        pg[tid] = logf(fabsf(Bp[tid]) + 1e-9f) + logf(fabsf(Cp[tid]) + 1e-9f);
    }

    for (int idx = tid; idx < 127 * 32; idx += 256) {
        const int j = idx >> 5, n = idx & 31;
        const int tq = t0 - 63 + j;
        xp_s[idx] = (tq >= 0) ? g_xp[((size_t)b * T_LEN + tq) * HALF + n] : 0.f;
    }
    __syncthreads();

    for (int idx = tid; idx < TAPS * 32; idx += 256) {
        const int s = idx >> 5, n = idx & 31;
        kk[s][n] = expf(pg[n] + (float)s * pl[n]) * cosf((float)s * pa[n]);
    }
    __syncthreads();

    {
        const int n  = tid & 31;
        const int tg = tid >> 5;
#pragma unroll
        for (int r = 0; r < 8; r++) {
            const int tl = tg * 8 + r;
            float acc = 0.f;
            const float* base = &xp_s[(tl + 63) * 32 + n];
#pragma unroll
            for (int s = 0; s < TAPS; s++) {
                acc += kk[s][n] * base[-s * 32];
            }
            y_s[tl][n] = acc;
        }
    }
    __syncthreads();

    // GEMM2: thread owns 4 consecutive d (d0=tid*4).
    // For each n-chunk of 8: keep W_out[4d][8n] in regs, stream y rows.
    const int d0 = tid * 4;
#pragma unroll 1
    for (int ttile = 0; ttile < TT / 8; ttile++) {
        const int tb = ttile * 8;
        float acc[8][4];
#pragma unroll
        for (int i = 0; i < 8; i++)
#pragma unroll
            for (int j = 0; j < 4; j++) acc[i][j] = 0.f;

#pragma unroll
        for (int nc = 0; nc < 4; nc++) {
            const int n0 = nc * 8;
            float4 w[4][2];
#pragma unroll
            for (int dd = 0; dd < 4; dd++) {
                const float4* wp = (const float4*)(W_out + (size_t)(d0 + dd) * HALF + n0);
                w[dd][0] = wp[0];
                w[dd][1] = wp[1];
            }
#pragma unroll
            for (int t8 = 0; t8 < 8; t8++) {
                float4 y0 = *(const float4*)&y_s[tb + t8][n0];
                float4 y1 = *(const float4*)&y_s[tb + t8][n0 + 4];
#pragma unroll
                for (int dd = 0; dd < 4; dd++) {
                    float a = acc[t8][dd];
                    a += y0.x * w[dd][0].x;
                    a += y0.y * w[dd][0].y;
                    a += y0.z * w[dd][0].z;
                    a += y0.w * w[dd][0].w;
                    a += y1.x * w[dd][1].x;
                    a += y1.y * w[dd][1].y;
                    a += y1.z * w[dd][1].z;
                    a += y1.w * w[dd][1].w;
                    acc[t8][dd] = a;
                }
            }
        }
#pragma unroll
        for (int t8 = 0; t8 < 8; t8++) {
            float4 o;
            o.x = acc[t8][0]; o.y = acc[t8][1]; o.z = acc[t8][2]; o.w = acc[t8][3];
            *(float4*)(out + ((size_t)b * T_LEN + t0 + tb + t8) * D_MODEL + d0) = o;
        }
    }
}

// ---------------------------------------------------------------------------
extern "C" void kernel_launch(void* const* d_in, const int* in_sizes, int n_in,
                              void* d_out, int out_size)
{
    const float* x       = (const float*)d_in[0];
    const float* log_tau = (const float*)d_in[1];
    const float* freq    = (const float*)d_in[2];
    const float* Bp      = (const float*)d_in[3];
    const float* Cp      = (const float*)d_in[4];
    const float* log_dt  = (const float*)d_in[5];
    const float* W_in    = (const float*)d_in[6];
    const float* W_out   = (const float*)d_in[7];
    float* out           = (float*)d_out;

    (void)in_sizes; (void)n_in; (void)out_size;

    cudaFuncSetAttribute(proj_mma_kernel,
                         cudaFuncAttributeMaxDynamicSharedMemorySize, SMEM_G1_BYTES);
    proj_mma_kernel<<<ROWS / 128, 256, SMEM_G1_BYTES>>>(x, W_in);
    conv_out_kernel<<<(BATCH * T_LEN) / TT, 256>>>(log_tau, freq, Bp, Cp, log_dt,
                                                   W_out, out);
}

// round 4
// speedup vs baseline: 3.4163x; 2.9156x over previous
#include <cuda_runtime.h>
#include <cstdint>

#define D_MODEL 1024
#define HALF    32
#define T_LEN   8192
#define BATCH   4
#define ROWS    (BATCH * T_LEN)   // 32768
#define TAPS    32
#define TT      64

// scratch: projected modes xp[row][n] fp32 (4 MB)
__device__ float g_xp[ROWS * HALF];
// conv output, packed bf16x2 pairs along n (k-dim of GEMM2), hi/lo split (2 MB each)
__device__ uint32_t g_yh[ROWS * 16];
__device__ uint32_t g_yl[ROWS * 16];

// ---------------------------------------------------------------------------
// bf16 helpers
// ---------------------------------------------------------------------------
// pack two fp32 -> bf16x2, f0 in LOW 16 bits, f1 in HIGH 16 bits
__device__ __forceinline__ uint32_t pack_bf2(float f0, float f1) {
    uint32_t d;
    asm("cvt.rn.bf16x2.f32 %0, %1, %2;" : "=r"(d) : "f"(f1), "f"(f0));
    return d;
}
// split a pair of fp32 into hi (bf16x2) and lo (residual bf16x2)
__device__ __forceinline__ void split_bf2(float f0, float f1, uint32_t& h, uint32_t& l) {
    h = pack_bf2(f0, f1);
    float f0h = __uint_as_float(h << 16);
    float f1h = __uint_as_float(h & 0xFFFF0000u);
    l = pack_bf2(f0 - f0h, f1 - f1h);
}

__device__ __forceinline__ void mma_bf16(float& c0, float& c1, float& c2, float& c3,
                                         uint32_t a0, uint32_t a1, uint32_t a2, uint32_t a3,
                                         uint32_t b0, uint32_t b1) {
    asm volatile(
        "mma.sync.aligned.m16n8k16.row.col.f32.bf16.bf16.f32 "
        "{%0,%1,%2,%3}, {%4,%5,%6,%7}, {%8,%9}, {%0,%1,%2,%3};"
        : "+f"(c0), "+f"(c1), "+f"(c2), "+f"(c3)
        : "r"(a0), "r"(a1), "r"(a2), "r"(a3), "r"(b0), "r"(b1));
}

#define RSTR 20   // u32 stride per row (16 data + 4 pad) -> conflict-free frags

// ===========================================================================
// K1: xp[row][n] = sum_d x[row][d] * W_in[n][d]   (bf16x3 split mma)
// CTA: 128 rows x 32 n, 256 thr (8 warps). K=1024 in 32 chunks of 32.
// Warp w: rows (w&3)*32..+32, cols (w>>2)*16..+16.
// ===========================================================================
__global__ void __launch_bounds__(256) proj_mma_kernel(const float* __restrict__ x,
                                                       const float* __restrict__ W_in)
{
    __shared__ uint32_t Ah[128 * RSTR], Al[128 * RSTR];
    __shared__ uint32_t Bh[32 * RSTR],  Bl[32 * RSTR];

    const int tid = threadIdx.x;
    const int wid = tid >> 5;
    const int lid = tid & 31;
    const int g   = lid >> 2;
    const int tig = lid & 3;
    const int row0 = blockIdx.x * 128;

    const int mroww = (wid & 3) * 32;
    const int ncolw = (wid >> 2) * 16;

    float4 pa[4];
    float4 pb;

    // prefetch chunk 0
#pragma unroll
    for (int p = 0; p < 4; p++) {
        const int f = tid + p * 256;
        pa[p] = *(const float4*)(x + (size_t)(row0 + (f >> 3)) * D_MODEL + (f & 7) * 4);
    }
    pb = *(const float4*)(W_in + (size_t)(tid >> 3) * D_MODEL + (tid & 7) * 4);

    // store chunk 0
    {
#pragma unroll
        for (int p = 0; p < 4; p++) {
            const int f = tid + p * 256;
            const int r = f >> 3, q = f & 7;
            uint32_t h0, l0, h1, l1;
            split_bf2(pa[p].x, pa[p].y, h0, l0);
            split_bf2(pa[p].z, pa[p].w, h1, l1);
            *(uint2*)&Ah[r * RSTR + q * 2] = make_uint2(h0, h1);
            *(uint2*)&Al[r * RSTR + q * 2] = make_uint2(l0, l1);
        }
        const int n = tid >> 3, q = tid & 7;
        uint32_t h0, l0, h1, l1;
        split_bf2(pb.x, pb.y, h0, l0);
        split_bf2(pb.z, pb.w, h1, l1);
        *(uint2*)&Bh[n * RSTR + q * 2] = make_uint2(h0, h1);
        *(uint2*)&Bl[n * RSTR + q * 2] = make_uint2(l0, l1);
    }

    float acc[2][2][4];
#pragma unroll
    for (int mt = 0; mt < 2; mt++)
#pragma unroll
        for (int nt = 0; nt < 2; nt++)
#pragma unroll
            for (int i = 0; i < 4; i++) acc[mt][nt][i] = 0.f;

#pragma unroll 1
    for (int c = 0; c < 32; c++) {
        __syncthreads();   // chunk c smem ready

        // prefetch chunk c+1
        if (c + 1 < 32) {
#pragma unroll
            for (int p = 0; p < 4; p++) {
                const int f = tid + p * 256;
                pa[p] = *(const float4*)(x + (size_t)(row0 + (f >> 3)) * D_MODEL +
                                         (c + 1) * 32 + (f & 7) * 4);
            }
            pb = *(const float4*)(W_in + (size_t)(tid >> 3) * D_MODEL +
                                  (c + 1) * 32 + (tid & 7) * 4);
        }

        // compute: 2 k16-steps
#pragma unroll
        for (int ks = 0; ks < 2; ks++) {
            const int kb = ks * 8;
            uint32_t ah[2][4], al_[2][4];
#pragma unroll
            for (int mt = 0; mt < 2; mt++) {
                const int r = mroww + mt * 16 + g;
                ah[mt][0]  = Ah[r * RSTR + kb + tig];
                ah[mt][1]  = Ah[(r + 8) * RSTR + kb + tig];
                ah[mt][2]  = Ah[r * RSTR + kb + tig + 4];
                ah[mt][3]  = Ah[(r + 8) * RSTR + kb + tig + 4];
                al_[mt][0] = Al[r * RSTR + kb + tig];
                al_[mt][1] = Al[(r + 8) * RSTR + kb + tig];
                al_[mt][2] = Al[r * RSTR + kb + tig + 4];
                al_[mt][3] = Al[(r + 8) * RSTR + kb + tig + 4];
            }
            uint32_t bh_[2][2], bl_[2][2];
#pragma unroll
            for (int nt = 0; nt < 2; nt++) {
                const int n = ncolw + nt * 8 + g;
                bh_[nt][0] = Bh[n * RSTR + kb + tig];
                bh_[nt][1] = Bh[n * RSTR + kb + tig + 4];
                bl_[nt][0] = Bl[n * RSTR + kb + tig];
                bl_[nt][1] = Bl[n * RSTR + kb + tig + 4];
            }
#pragma unroll
            for (int mt = 0; mt < 2; mt++)
#pragma unroll
                for (int nt = 0; nt < 2; nt++) {
                    float* cc = acc[mt][nt];
                    mma_bf16(cc[0], cc[1], cc[2], cc[3],
                             ah[mt][0], ah[mt][1], ah[mt][2], ah[mt][3],
                             bh_[nt][0], bh_[nt][1]);
                    mma_bf16(cc[0], cc[1], cc[2], cc[3],
                             ah[mt][0], ah[mt][1], ah[mt][2], ah[mt][3],
                             bl_[nt][0], bl_[nt][1]);
                    mma_bf16(cc[0], cc[1], cc[2], cc[3],
                             al_[mt][0], al_[mt][1], al_[mt][2], al_[mt][3],
                             bh_[nt][0], bh_[nt][1]);
                }
        }

        __syncthreads();   // reads of chunk c done

        if (c + 1 < 32) {
#pragma unroll
            for (int p = 0; p < 4; p++) {
                const int f = tid + p * 256;
                const int r = f >> 3, q = f & 7;
                uint32_t h0, l0, h1, l1;
                split_bf2(pa[p].x, pa[p].y, h0, l0);
                split_bf2(pa[p].z, pa[p].w, h1, l1);
                *(uint2*)&Ah[r * RSTR + q * 2] = make_uint2(h0, h1);
                *(uint2*)&Al[r * RSTR + q * 2] = make_uint2(l0, l1);
            }
            const int n = tid >> 3, q = tid & 7;
            uint32_t h0, l0, h1, l1;
            split_bf2(pb.x, pb.y, h0, l0);
            split_bf2(pb.z, pb.w, h1, l1);
            *(uint2*)&Bh[n * RSTR + q * 2] = make_uint2(h0, h1);
            *(uint2*)&Bl[n * RSTR + q * 2] = make_uint2(l0, l1);
        }
    }

    // epilogue: c0,c1 -> (row g, cols 2tig..), c2,c3 -> row g+8
#pragma unroll
    for (int mt = 0; mt < 2; mt++) {
        const int r0 = row0 + mroww + mt * 16 + g;
#pragma unroll
        for (int nt = 0; nt < 2; nt++) {
            const int col = ncolw + nt * 8 + tig * 2;
            *(float2*)(g_xp + (size_t)r0 * HALF + col) =
                make_float2(acc[mt][nt][0], acc[mt][nt][1]);
            *(float2*)(g_xp + (size_t)(r0 + 8) * HALF + col) =
                make_float2(acc[mt][nt][2], acc[mt][nt][3]);
        }
    }
}

// ===========================================================================
// K2: FIR taps + causal conv; writes y split hi/lo packed bf16x2 (pairs along n)
// ===========================================================================
__global__ void __launch_bounds__(256) conv_kernel(
    const float* __restrict__ log_tau, const float* __restrict__ freq,
    const float* __restrict__ Bp,      const float* __restrict__ Cp,
    const float* __restrict__ log_dt)
{
    __shared__ float xp_s[(TT + TAPS - 1) * 32];   // 95 rows
    __shared__ float kk[TAPS][32];
    __shared__ float y_s[TT][32];
    __shared__ float pg[32], pl[32], pa[32];

    const int tid = threadIdx.x;
    const int blk = blockIdx.x;
    const int b   = blk >> 7;
    const int t0  = (blk & 127) * TT;

    if (tid < 32) {
        float dt  = expf(log_dt[0]);
        float tau = fmaxf(expf(log_tau[tid]), 1e-4f);
        pl[tid] = -tau * dt;
        pa[tid] = freq[tid] * dt;
        pg[tid] = logf(fabsf(Bp[tid]) + 1e-9f) + logf(fabsf(Cp[tid]) + 1e-9f);
    }

    for (int idx = tid; idx < (TT + TAPS - 1) * 32; idx += 256) {
        const int j = idx >> 5, n = idx & 31;
        const int tq = t0 - (TAPS - 1) + j;
        xp_s[idx] = (tq >= 0) ? g_xp[((size_t)b * T_LEN + tq) * HALF + n] : 0.f;
    }
    __syncthreads();

    for (int idx = tid; idx < TAPS * 32; idx += 256) {
        const int s = idx >> 5, n = idx & 31;
        kk[s][n] = expf(pg[n] + (float)s * pl[n]) * cosf((float)s * pa[n]);
    }
    __syncthreads();

    {
        const int n  = tid & 31;
        const int tg = tid >> 5;
#pragma unroll
        for (int r = 0; r < 8; r++) {
            const int tl = tg * 8 + r;
            float acc = 0.f;
            const float* base = &xp_s[(tl + TAPS - 1) * 32 + n];
#pragma unroll
            for (int s = 0; s < TAPS; s++) {
                acc += kk[s][n] * base[-s * 32];
            }
            y_s[tl][n] = acc;
        }
    }
    __syncthreads();

    // pack + write: 64 t x 16 kp
    for (int idx = tid; idx < TT * 16; idx += 256) {
        const int t = idx >> 4, kp = idx & 15;
        uint32_t h, l;
        split_bf2(y_s[t][2 * kp], y_s[t][2 * kp + 1], h, l);
        const size_t row = (size_t)b * T_LEN + t0 + t;
        g_yh[row * 16 + kp] = h;
        g_yl[row * 16 + kp] = l;
    }
}

// ===========================================================================
// K3: GEMM2  out[t][d] = sum_n y[t][n] * W_out[d][n]   (bf16x3 split mma)
// CTA: 128 t x 256 d, 256 thr. grid (256, 4).
// Warp w: m-group (w&3) -> 2 m16 strips; d-group (w>>2) -> 16 chunks of 8 d.
// ===========================================================================
#define K3_SMEM_BYTES ((128 * RSTR + 128 * RSTR + 256 * RSTR + 256 * RSTR) * 4)

__global__ void __launch_bounds__(256) gemm2_kernel(const float* __restrict__ W_out,
                                                    float* __restrict__ out)
{
    extern __shared__ uint32_t sm3[];
    uint32_t* Ah = sm3;
    uint32_t* Al = Ah + 128 * RSTR;
    uint32_t* Bh = Al + 128 * RSTR;
    uint32_t* Bl = Bh + 256 * RSTR;

    const int tid = threadIdx.x;
    const int wid = tid >> 5;
    const int lid = tid & 31;
    const int g   = lid >> 2;
    const int tig = lid & 3;

    const int t0 = blockIdx.x * 128;
    const int d0 = blockIdx.y * 256;

    // stage A (already split/packed): 128 rows x 16 u32, hi & lo
#pragma unroll
    for (int p = 0; p < 2; p++) {
        const int f = tid + p * 256;
        const int r = f >> 2, q4 = (f & 3) * 4;
        *(uint4*)&Ah[r * RSTR + q4] = *(const uint4*)&g_yh[(size_t)(t0 + r) * 16 + q4];
        *(uint4*)&Al[r * RSTR + q4] = *(const uint4*)&g_yl[(size_t)(t0 + r) * 16 + q4];
    }
    // stage B: W_out slice 256 rows x 32 fp32 -> split pack
#pragma unroll
    for (int p = 0; p < 8; p++) {
        const int f = tid + p * 256;
        const int r = f >> 3, q = f & 7;
        float4 v = *(const float4*)(W_out + (size_t)(d0 + r) * HALF + q * 4);
        uint32_t h0, l0, h1, l1;
        split_bf2(v.x, v.y, h0, l0);
        split_bf2(v.z, v.w, h1, l1);
        *(uint2*)&Bh[r * RSTR + q * 2] = make_uint2(h0, h1);
        *(uint2*)&Bl[r * RSTR + q * 2] = make_uint2(l0, l1);
    }
    __syncthreads();

    const int mg = wid & 3;
    const int dg = wid >> 2;

    // A fragments, loaded once: [mt][ks][4] hi/lo
    uint32_t afh[2][2][4], afl[2][2][4];
#pragma unroll
    for (int mt = 0; mt < 2; mt++) {
        const int r = mg * 32 + mt * 16 + g;
#pragma unroll
        for (int ks = 0; ks < 2; ks++) {
            const int kb = ks * 8;
            afh[mt][ks][0] = Ah[r * RSTR + kb + tig];
            afh[mt][ks][1] = Ah[(r + 8) * RSTR + kb + tig];
            afh[mt][ks][2] = Ah[r * RSTR + kb + tig + 4];
            afh[mt][ks][3] = Ah[(r + 8) * RSTR + kb + tig + 4];
            afl[mt][ks][0] = Al[r * RSTR + kb + tig];
            afl[mt][ks][1] = Al[(r + 8) * RSTR + kb + tig];
            afl[mt][ks][2] = Al[r * RSTR + kb + tig + 4];
            afl[mt][ks][3] = Al[(r + 8) * RSTR + kb + tig + 4];
        }
    }

#pragma unroll 1
    for (int ch = 0; ch < 16; ch++) {
        const int nb = dg * 128 + ch * 8;   // local d base of this 8-wide chunk
        float acc[2][4];
#pragma unroll
        for (int mt = 0; mt < 2; mt++)
#pragma unroll
            for (int i = 0; i < 4; i++) acc[mt][i] = 0.f;

#pragma unroll
        for (int ks = 0; ks < 2; ks++) {
            const int kb = ks * 8;
            const int nr = nb + g;
            uint32_t bh0 = Bh[nr * RSTR + kb + tig];
            uint32_t bh1 = Bh[nr * RSTR + kb + tig + 4];
            uint32_t bl0 = Bl[nr * RSTR + kb + tig];
            uint32_t bl1 = Bl[nr * RSTR + kb + tig + 4];
#pragma unroll
            for (int mt = 0; mt < 2; mt++) {
                float* cc = acc[mt];
                mma_bf16(cc[0], cc[1], cc[2], cc[3],
                         afh[mt][ks][0], afh[mt][ks][1], afh[mt][ks][2], afh[mt][ks][3],
                         bh0, bh1);
                mma_bf16(cc[0], cc[1], cc[2], cc[3],
                         afh[mt][ks][0], afh[mt][ks][1], afh[mt][ks][2], afh[mt][ks][3],
                         bl0, bl1);
                mma_bf16(cc[0], cc[1], cc[2], cc[3],
                         afl[mt][ks][0], afl[mt][ks][1], afl[mt][ks][2], afl[mt][ks][3],
                         bh0, bh1);
            }
        }

        const int col = d0 + nb + tig * 2;
#pragma unroll
        for (int mt = 0; mt < 2; mt++) {
            const int tr = t0 + mg * 32 + mt * 16 + g;
            *(float2*)(out + (size_t)tr * D_MODEL + col) =
                make_float2(acc[mt][0], acc[mt][1]);
            *(float2*)(out + (size_t)(tr + 8) * D_MODEL + col) =
                make_float2(acc[mt][2], acc[mt][3]);
        }
    }
}

// ---------------------------------------------------------------------------
extern "C" void kernel_launch(void* const* d_in, const int* in_sizes, int n_in,
                              void* d_out, int out_size)
{
    const float* x       = (const float*)d_in[0];
    const float* log_tau = (const float*)d_in[1];
    const float* freq    = (const float*)d_in[2];
    const float* Bp      = (const float*)d_in[3];
    const float* Cp      = (const float*)d_in[4];
    const float* log_dt  = (const float*)d_in[5];
    const float* W_in    = (const float*)d_in[6];
    const float* W_out   = (const float*)d_in[7];
    float* out           = (float*)d_out;

    (void)in_sizes; (void)n_in; (void)out_size;

    static bool attr_set = false;
    if (!attr_set) {
        cudaFuncSetAttribute(gemm2_kernel,
                             cudaFuncAttributeMaxDynamicSharedMemorySize, K3_SMEM_BYTES);
        attr_set = true;
    }

    proj_mma_kernel<<<ROWS / 128, 256>>>(x, W_in);
    conv_kernel<<<(BATCH * T_LEN) / TT, 256>>>(log_tau, freq, Bp, Cp, log_dt);
    gemm2_kernel<<<dim3(ROWS / 128, D_MODEL / 256), 256, K3_SMEM_BYTES>>>(W_out, out);
}

// round 6
// speedup vs baseline: 3.5566x; 1.0411x over previous
#include <cuda_runtime.h>
#include <cstdint>

#define D_MODEL 1024
#define HALF    32
#define T_LEN   8192
#define BATCH   4
#define ROWS    (BATCH * T_LEN)   // 32768
#define TAPS    32
#define TT      64
#define RSTR    20   // u32 stride per smem row (16 data + 4 pad)

// scratch: projected modes xp[row][n] fp32 (4 MB)
__device__ float g_xp[ROWS * HALF];
// conv output, packed bf16x2 pairs along n, hi/lo split (2 MB each)
__device__ uint32_t g_yh[ROWS * 16];
__device__ uint32_t g_yl[ROWS * 16];

// ---------------------------------------------------------------------------
// bf16 helpers
// ---------------------------------------------------------------------------
__device__ __forceinline__ uint32_t pack_bf2(float f0, float f1) {
    uint32_t d;
    asm("cvt.rn.bf16x2.f32 %0, %1, %2;" : "=r"(d) : "f"(f1), "f"(f0));
    return d;
}
__device__ __forceinline__ void split_bf2(float f0, float f1, uint32_t& h, uint32_t& l) {
    h = pack_bf2(f0, f1);
    float f0h = __uint_as_float(h << 16);
    float f1h = __uint_as_float(h & 0xFFFF0000u);
    l = pack_bf2(f0 - f0h, f1 - f1h);
}
__device__ __forceinline__ void mma_bf16(float& c0, float& c1, float& c2, float& c3,
                                         uint32_t a0, uint32_t a1, uint32_t a2, uint32_t a3,
                                         uint32_t b0, uint32_t b1) {
    asm volatile(
        "mma.sync.aligned.m16n8k16.row.col.f32.bf16.bf16.f32 "
        "{%0,%1,%2,%3}, {%4,%5,%6,%7}, {%8,%9}, {%0,%1,%2,%3};"
        : "+f"(c0), "+f"(c1), "+f"(c2), "+f"(c3)
        : "r"(a0), "r"(a1), "r"(a2), "r"(a3), "r"(b0), "r"(b1));
}

// ===========================================================================
// K1: xp[row][n] = sum_d x[row][d]*W_in[n][d]  (bf16x3 split, double-buffered)
// CTA: 128 rows x 32 n, 256 thr. K=1024 in 32 chunks of 32, 1 sync/chunk.
// ===========================================================================
#define K1_STAGE      6400                // u32 per stage: A 2x2560 + B 2x640
#define K1_SMEM_BYTES (2 * K1_STAGE * 4)  // 51.2 KB

__global__ void __launch_bounds__(256) proj_mma_kernel(const float* __restrict__ x,
                                                       const float* __restrict__ W_in)
{
    extern __shared__ uint32_t sm1[];
    const int tid = threadIdx.x;
    const int wid = tid >> 5;
    const int lid = tid & 31;
    const int g   = lid >> 2;
    const int tig = lid & 3;
    const int row0 = blockIdx.x * 128;

    const int mroww = (wid & 3) * 32;
    const int ncolw = (wid >> 2) * 16;

    float4 pa[4];
    float4 pb;

    auto ldg_chunk = [&](int c) {
#pragma unroll
        for (int p = 0; p < 4; p++) {
            const int f = tid + p * 256;
            pa[p] = *(const float4*)(x + (size_t)(row0 + (f >> 3)) * D_MODEL +
                                     c * 32 + (f & 7) * 4);
        }
        pb = *(const float4*)(W_in + (size_t)(tid >> 3) * D_MODEL + c * 32 + (tid & 7) * 4);
    };
    auto sts_chunk = [&](int buf) {
        uint32_t* Ah = sm1 + buf * K1_STAGE;
        uint32_t* Al = Ah + 2560;
        uint32_t* Bh = Ah + 5120;
        uint32_t* Bl = Ah + 5760;
#pragma unroll
        for (int p = 0; p < 4; p++) {
            const int f = tid + p * 256;
            const int r = f >> 3, q = f & 7;
            uint32_t h0, l0, h1, l1;
            split_bf2(pa[p].x, pa[p].y, h0, l0);
            split_bf2(pa[p].z, pa[p].w, h1, l1);
            *(uint2*)&Ah[r * RSTR + q * 2] = make_uint2(h0, h1);
            *(uint2*)&Al[r * RSTR + q * 2] = make_uint2(l0, l1);
        }
        const int n = tid >> 3, q = tid & 7;
        uint32_t h0, l0, h1, l1;
        split_bf2(pb.x, pb.y, h0, l0);
        split_bf2(pb.z, pb.w, h1, l1);
        *(uint2*)&Bh[n * RSTR + q * 2] = make_uint2(h0, h1);
        *(uint2*)&Bl[n * RSTR + q * 2] = make_uint2(l0, l1);
    };

    ldg_chunk(0);
    sts_chunk(0);
    ldg_chunk(1);
    __syncthreads();

    float acc[2][2][4];
#pragma unroll
    for (int mt = 0; mt < 2; mt++)
#pragma unroll
        for (int nt = 0; nt < 2; nt++)
#pragma unroll
            for (int i = 0; i < 4; i++) acc[mt][nt][i] = 0.f;

#pragma unroll 1
    for (int c = 0; c < 32; c++) {
        if (c + 1 < 32) sts_chunk((c + 1) & 1);
        if (c + 2 < 32) ldg_chunk(c + 2);

        const uint32_t* Ah = sm1 + (c & 1) * K1_STAGE;
        const uint32_t* Al = Ah + 2560;
        const uint32_t* Bh = Ah + 5120;
        const uint32_t* Bl = Ah + 5760;

#pragma unroll
        for (int ks = 0; ks < 2; ks++) {
            const int kb = ks * 8;
            uint32_t ah[2][4], al_[2][4];
#pragma unroll
            for (int mt = 0; mt < 2; mt++) {
                const int r = mroww + mt * 16 + g;
                ah[mt][0]  = Ah[r * RSTR + kb + tig];
                ah[mt][1]  = Ah[(r + 8) * RSTR + kb + tig];
                ah[mt][2]  = Ah[r * RSTR + kb + tig + 4];
                ah[mt][3]  = Ah[(r + 8) * RSTR + kb + tig + 4];
                al_[mt][0] = Al[r * RSTR + kb + tig];
                al_[mt][1] = Al[(r + 8) * RSTR + kb + tig];
                al_[mt][2] = Al[r * RSTR + kb + tig + 4];
                al_[mt][3] = Al[(r + 8) * RSTR + kb + tig + 4];
            }
            uint32_t bh_[2][2], bl_[2][2];
#pragma unroll
            for (int nt = 0; nt < 2; nt++) {
                const int n = ncolw + nt * 8 + g;
                bh_[nt][0] = Bh[n * RSTR + kb + tig];
                bh_[nt][1] = Bh[n * RSTR + kb + tig + 4];
                bl_[nt][0] = Bl[n * RSTR + kb + tig];
                bl_[nt][1] = Bl[n * RSTR + kb + tig + 4];
            }
#pragma unroll
            for (int mt = 0; mt < 2; mt++)
#pragma unroll
                for (int nt = 0; nt < 2; nt++) {
                    float* cc = acc[mt][nt];
                    mma_bf16(cc[0], cc[1], cc[2], cc[3],
                             ah[mt][0], ah[mt][1], ah[mt][2], ah[mt][3],
                             bh_[nt][0], bh_[nt][1]);
                    mma_bf16(cc[0], cc[1], cc[2], cc[3],
                             ah[mt][0], ah[mt][1], ah[mt][2], ah[mt][3],
                             bl_[nt][0], bl_[nt][1]);
                    mma_bf16(cc[0], cc[1], cc[2], cc[3],
                             al_[mt][0], al_[mt][1], al_[mt][2], al_[mt][3],
                             bh_[nt][0], bh_[nt][1]);
                }
        }
        __syncthreads();
    }

#pragma unroll
    for (int mt = 0; mt < 2; mt++) {
        const int r0 = row0 + mroww + mt * 16 + g;
#pragma unroll
        for (int nt = 0; nt < 2; nt++) {
            const int col = ncolw + nt * 8 + tig * 2;
            *(float2*)(g_xp + (size_t)r0 * HALF + col) =
                make_float2(acc[mt][nt][0], acc[mt][nt][1]);
            *(float2*)(g_xp + (size_t)(r0 + 8) * HALF + col) =
                make_float2(acc[mt][nt][2], acc[mt][nt][3]);
        }
    }
}

// ===========================================================================
// K2: FIR taps + causal conv; writes y split hi/lo packed bf16x2 (R4-proven)
// ===========================================================================
__global__ void __launch_bounds__(256) conv_kernel(
    const float* __restrict__ log_tau, const float* __restrict__ freq,
    const float* __restrict__ Bp,      const float* __restrict__ Cp,
    const float* __restrict__ log_dt)
{
    __shared__ float xp_s[(TT + TAPS - 1) * 32];   // 95 rows
    __shared__ float kk[TAPS][32];
    __shared__ float y_s[TT][32];
    __shared__ float pg[32], pl[32], pa[32];

    const int tid = threadIdx.x;
    const int blk = blockIdx.x;
    const int b   = blk >> 7;
    const int t0  = (blk & 127) * TT;

    if (tid < 32) {
        float dt  = expf(log_dt[0]);
        float tau = fmaxf(expf(log_tau[tid]), 1e-4f);
        pl[tid] = -tau * dt;
        pa[tid] = freq[tid] * dt;
        pg[tid] = logf(fabsf(Bp[tid]) + 1e-9f) + logf(fabsf(Cp[tid]) + 1e-9f);
    }

    for (int idx = tid; idx < (TT + TAPS - 1) * 32; idx += 256) {
        const int j = idx >> 5, n = idx & 31;
        const int tq = t0 - (TAPS - 1) + j;
        xp_s[idx] = (tq >= 0) ? g_xp[((size_t)b * T_LEN + tq) * HALF + n] : 0.f;
    }
    __syncthreads();

    for (int idx = tid; idx < TAPS * 32; idx += 256) {
        const int s = idx >> 5, n = idx & 31;
        kk[s][n] = expf(pg[n] + (float)s * pl[n]) * cosf((float)s * pa[n]);
    }
    __syncthreads();

    {
        const int n  = tid & 31;
        const int tg = tid >> 5;
#pragma unroll
        for (int r = 0; r < 8; r++) {
            const int tl = tg * 8 + r;
            float acc = 0.f;
            const float* base = &xp_s[(tl + TAPS - 1) * 32 + n];
#pragma unroll
            for (int s = 0; s < TAPS; s++) {
                acc += kk[s][n] * base[-s * 32];
            }
            y_s[tl][n] = acc;
        }
    }
    __syncthreads();

    for (int idx = tid; idx < TT * 16; idx += 256) {
        const int t = idx >> 4, kp = idx & 15;
        uint32_t h, l;
        split_bf2(y_s[t][2 * kp], y_s[t][2 * kp + 1], h, l);
        const size_t row = (size_t)b * T_LEN + t0 + t;
        g_yh[row * 16 + kp] = h;
        g_yl[row * 16 + kp] = l;
    }
}

// ===========================================================================
// K3: GEMM2  out[t][d] = sum_n y[t][n] * W_out[d][n]   (R4-proven)
// ===========================================================================
#define K3_SMEM_BYTES ((128 * RSTR + 128 * RSTR + 256 * RSTR + 256 * RSTR) * 4)

__global__ void __launch_bounds__(256) gemm2_kernel(const float* __restrict__ W_out,
                                                    float* __restrict__ out)
{
    extern __shared__ uint32_t sm3[];
    uint32_t* Ah = sm3;
    uint32_t* Al = Ah + 128 * RSTR;
    uint32_t* Bh = Al + 128 * RSTR;
    uint32_t* Bl = Bh + 256 * RSTR;

    const int tid = threadIdx.x;
    const int wid = tid >> 5;
    const int lid = tid & 31;
    const int g   = lid >> 2;
    const int tig = lid & 3;

    const int t0 = blockIdx.x * 128;
    const int d0 = blockIdx.y * 256;

#pragma unroll
    for (int p = 0; p < 2; p++) {
        const int f = tid + p * 256;
        const int r = f >> 2, q4 = (f & 3) * 4;
        *(uint4*)&Ah[r * RSTR + q4] = *(const uint4*)&g_yh[(size_t)(t0 + r) * 16 + q4];
        *(uint4*)&Al[r * RSTR + q4] = *(const uint4*)&g_yl[(size_t)(t0 + r) * 16 + q4];
    }
#pragma unroll
    for (int p = 0; p < 8; p++) {
        const int f = tid + p * 256;
        const int r = f >> 3, q = f & 7;
        float4 v = *(const float4*)(W_out + (size_t)(d0 + r) * HALF + q * 4);
        uint32_t h0, l0, h1, l1;
        split_bf2(v.x, v.y, h0, l0);
        split_bf2(v.z, v.w, h1, l1);
        *(uint2*)&Bh[r * RSTR + q * 2] = make_uint2(h0, h1);
        *(uint2*)&Bl[r * RSTR + q * 2] = make_uint2(l0, l1);
    }
    __syncthreads();

    const int mg = wid & 3;
    const int dg = wid >> 2;

    uint32_t afh[2][2][4], afl[2][2][4];
#pragma unroll
    for (int mt = 0; mt < 2; mt++) {
        const int r = mg * 32 + mt * 16 + g;
#pragma unroll
        for (int ks = 0; ks < 2; ks++) {
            const int kb = ks * 8;
            afh[mt][ks][0] = Ah[r * RSTR + kb + tig];
            afh[mt][ks][1] = Ah[(r + 8) * RSTR + kb + tig];
            afh[mt][ks][2] = Ah[r * RSTR + kb + tig + 4];
            afh[mt][ks][3] = Ah[(r + 8) * RSTR + kb + tig + 4];
            afl[mt][ks][0] = Al[r * RSTR + kb + tig];
            afl[mt][ks][1] = Al[(r + 8) * RSTR + kb + tig];
            afl[mt][ks][2] = Al[r * RSTR + kb + tig + 4];
            afl[mt][ks][3] = Al[(r + 8) * RSTR + kb + tig + 4];
        }
    }

#pragma unroll 1
    for (int ch = 0; ch < 16; ch++) {
        const int nb = dg * 128 + ch * 8;
        float acc[2][4];
#pragma unroll
        for (int mt = 0; mt < 2; mt++)
#pragma unroll
            for (int i = 0; i < 4; i++) acc[mt][i] = 0.f;

#pragma unroll
        for (int ks = 0; ks < 2; ks++) {
            const int kb = ks * 8;
            const int nr = nb + g;
            uint32_t bh0 = Bh[nr * RSTR + kb + tig];
            uint32_t bh1 = Bh[nr * RSTR + kb + tig + 4];
            uint32_t bl0 = Bl[nr * RSTR + kb + tig];
            uint32_t bl1 = Bl[nr * RSTR + kb + tig + 4];
#pragma unroll
            for (int mt = 0; mt < 2; mt++) {
                float* cc = acc[mt];
                mma_bf16(cc[0], cc[1], cc[2], cc[3],
                         afh[mt][ks][0], afh[mt][ks][1], afh[mt][ks][2], afh[mt][ks][3],
                         bh0, bh1);
                mma_bf16(cc[0], cc[1], cc[2], cc[3],
                         afh[mt][ks][0], afh[mt][ks][1], afh[mt][ks][2], afh[mt][ks][3],
                         bl0, bl1);
                mma_bf16(cc[0], cc[1], cc[2], cc[3],
                         afl[mt][ks][0], afl[mt][ks][1], afl[mt][ks][2], afl[mt][ks][3],
                         bh0, bh1);
            }
        }

        const int col = d0 + nb + tig * 2;
#pragma unroll
        for (int mt = 0; mt < 2; mt++) {
            const int tr = t0 + mg * 32 + mt * 16 + g;
            *(float2*)(out + (size_t)tr * D_MODEL + col) =
                make_float2(acc[mt][0], acc[mt][1]);
            *(float2*)(out + (size_t)(tr + 8) * D_MODEL + col) =
                make_float2(acc[mt][2], acc[mt][3]);
        }
    }
}

// ---------------------------------------------------------------------------
extern "C" void kernel_launch(void* const* d_in, const int* in_sizes, int n_in,
                              void* d_out, int out_size)
{
    const float* x       = (const float*)d_in[0];
    const float* log_tau = (const float*)d_in[1];
    const float* freq    = (const float*)d_in[2];
    const float* Bp      = (const float*)d_in[3];
    const float* Cp      = (const float*)d_in[4];
    const float* log_dt  = (const float*)d_in[5];
    const float* W_in    = (const float*)d_in[6];
    const float* W_out   = (const float*)d_in[7];
    float* out           = (float*)d_out;

    (void)in_sizes; (void)n_in; (void)out_size;

    static bool attr_set = false;
    if (!attr_set) {
        cudaFuncSetAttribute(proj_mma_kernel,
                             cudaFuncAttributeMaxDynamicSharedMemorySize, K1_SMEM_BYTES);
        cudaFuncSetAttribute(gemm2_kernel,
                             cudaFuncAttributeMaxDynamicSharedMemorySize, K3_SMEM_BYTES);
        attr_set = true;
    }

    proj_mma_kernel<<<ROWS / 128, 256, K1_SMEM_BYTES>>>(x, W_in);
    conv_kernel<<<(BATCH * T_LEN) / TT, 256>>>(log_tau, freq, Bp, Cp, log_dt);
    gemm2_kernel<<<dim3(ROWS / 128, D_MODEL / 256), 256, K3_SMEM_BYTES>>>(W_out, out);
}